// round 15
// baseline (speedup 1.0000x reference)
#include <cuda_runtime.h>
#include <cuda_fp16.h>
#include <math.h>
#include <stdint.h>

// URNNCell: out = modrelu( complex(inputs@W^T) + D3·R2·IFFT·D2·P·R1·FFT·D1·state_c )
// B=8192, N_IN=1024, N=2048 (complex), 2N=4096.

#define N_FFT   2048
#define BATCH   8192
#define NIN     1024
#define TWO_N   4096
#define SW(i)   ((i) + ((i) >> 5))

// ---------------- device scratch ----------------
__device__ float  g_inputs_mul[(size_t)BATCH * TWO_N];
__device__ __half g_Ah[(size_t)BATCH * NIN];
__device__ __half g_Wh[(size_t)TWO_N * NIN];
__device__ float2 g_d1cs[N_FFT], g_d2cs[N_FFT], g_d3cs[N_FFT];   // d3 premul by 1/N
__device__ float2 g_r1[N_FFT], g_r2[N_FFT];                      // interleaved reflection vectors
__device__ float2 g_tw[257];
__device__ float  g_fac1, g_fac2;

// ---------------- helpers ----------------
__device__ __forceinline__ uint32_t smem_u32(const void* p) {
    uint32_t a;
    asm("{ .reg .u64 t; cvta.to.shared.u64 t, %1; cvt.u32.u64 %0, t; }" : "=r"(a) : "l"(p));
    return a;
}
__device__ __forceinline__ void cp_async16_s(uint32_t saddr, const void* g) {
    asm volatile("cp.async.cg.shared.global [%0], [%1], 16;\n" :: "r"(saddr), "l"(g));
}
__device__ __forceinline__ void cp_commit() { asm volatile("cp.async.commit_group;\n"); }
template<int N> __device__ __forceinline__ void cp_wait() { asm volatile("cp.async.wait_group %0;\n" :: "n"(N)); }

__device__ __forceinline__ void ldmatrix_x4(uint32_t& r0, uint32_t& r1, uint32_t& r2, uint32_t& r3, uint32_t a) {
    asm volatile("ldmatrix.sync.aligned.m8n8.x4.shared.b16 {%0,%1,%2,%3}, [%4];"
                 : "=r"(r0), "=r"(r1), "=r"(r2), "=r"(r3) : "r"(a));
}
__device__ __forceinline__ void mma_f16(float& c0, float& c1, float& c2, float& c3,
                                        uint32_t a0, uint32_t a1, uint32_t a2, uint32_t a3,
                                        uint32_t b0, uint32_t b1) {
    asm volatile("mma.sync.aligned.m16n8k16.row.col.f32.f16.f16.f32 "
                 "{%0,%1,%2,%3}, {%4,%5,%6,%7}, {%8,%9}, {%0,%1,%2,%3};"
                 : "+f"(c0), "+f"(c1), "+f"(c2), "+f"(c3)
                 : "r"(a0), "r"(a1), "r"(a2), "r"(a3), "r"(b0), "r"(b1));
}

// ---------------- setup (1024 threads, forked stream) ----------------
__global__ void setup_kernel(const float* __restrict__ d1,
                             const float* __restrict__ r1re, const float* __restrict__ r1im,
                             const float* __restrict__ d2,
                             const float* __restrict__ r2re, const float* __restrict__ r2im,
                             const float* __restrict__ d3) {
    int tid = threadIdx.x;   // 1024
    const float invN = 1.f / (float)N_FFT;
    float p1 = 0.f, p2 = 0.f;
    for (int i = tid; i < N_FFT; i += 1024) {
        float s, c;
        sincosf(d1[i], &s, &c); g_d1cs[i] = make_float2(c, s);
        sincosf(d2[i], &s, &c); g_d2cs[i] = make_float2(c, s);
        sincosf(d3[i], &s, &c); g_d3cs[i] = make_float2(c * invN, s * invN);
        float v1r = r1re[i], v1i = r1im[i];
        float v2r = r2re[i], v2i = r2im[i];
        g_r1[i] = make_float2(v1r, v1i);
        g_r2[i] = make_float2(v2r, v2i);
        p1 += v1r * v1r + v1i * v1i;
        p2 += v2r * v2r + v2i * v2i;
    }
    if (tid < 257) {
        float s, c;
        sincosf(-6.283185307179586f * (float)tid / (float)N_FFT, &s, &c);
        g_tw[tid] = make_float2(c, s);
    }
    __shared__ float sh1[32], sh2[32];
    unsigned m = 0xffffffffu;
    for (int o = 16; o; o >>= 1) { p1 += __shfl_down_sync(m, p1, o); p2 += __shfl_down_sync(m, p2, o); }
    int w = tid >> 5, l = tid & 31;
    if (l == 0) { sh1[w] = p1; sh2[w] = p2; }
    __syncthreads();
    if (w == 0) {
        p1 = sh1[l]; p2 = sh2[l];
        for (int o = 16; o; o >>= 1) { p1 += __shfl_down_sync(m, p1, o); p2 += __shfl_down_sync(m, p2, o); }
        if (l == 0) { g_fac1 = 2.f / p1; g_fac2 = 2.f / p2; }
    }
}

// ---------------- fp32 -> fp16 convert ----------------
__global__ __launch_bounds__(256) void convert_kernel(const float* __restrict__ A,
                                                      const float* __restrict__ W) {
    size_t idx = ((size_t)blockIdx.x * 256 + threadIdx.x) * 8;
    const size_t NA = (size_t)BATCH * NIN;
    if (idx < NA) {
        float4 f0 = *(const float4*)(A + idx);
        float4 f1 = *(const float4*)(A + idx + 4);
        __half2* dst = (__half2*)(g_Ah + idx);
        dst[0] = __floats2half2_rn(f0.x, f0.y);
        dst[1] = __floats2half2_rn(f0.z, f0.w);
        dst[2] = __floats2half2_rn(f1.x, f1.y);
        dst[3] = __floats2half2_rn(f1.z, f1.w);
    } else {
        size_t j = idx - NA;
        float4 f0 = *(const float4*)(W + j);
        float4 f1 = *(const float4*)(W + j + 4);
        __half2* dst = (__half2*)(g_Wh + j);
        dst[0] = __floats2half2_rn(f0.x, f0.y);
        dst[1] = __floats2half2_rn(f0.z, f0.w);
        dst[2] = __floats2half2_rn(f1.x, f1.y);
        dst[3] = __floats2half2_rn(f1.z, f1.w);
    }
}

// ---------------- fp16 mma.sync GEMM (round-13 body, bm_base param) ----------------
#define KC 64
#define NCHUNK (NIN / KC)
#define HSTR 72
#define TILE_H (128 * HSTR)
#define STAGE_H (2 * TILE_H)
#define GEMM_SMEM (3 * STAGE_H * 2)

__global__ __launch_bounds__(512, 2) void gemm_f16(int bm_base) {
    extern __shared__ __half hsm[];
    int tid  = threadIdx.x;
    int lane = tid & 31;
    int warp = tid >> 5;
    int wm = warp >> 2;
    int wn = warp & 3;
    int bm = bm_base + blockIdx.y, bn = blockIdx.x;

    const __half* Ag = g_Ah + (size_t)bm * 128 * NIN;
    const __half* Wg = g_Wh + (size_t)bn * 128 * NIN;

    int crow[2], cseg[2];
    #pragma unroll
    for (int r = 0; r < 2; r++) { int idx = tid + 512 * r; crow[r] = idx >> 3; cseg[r] = idx & 7; }

    uint32_t sbase = smem_u32(hsm);

    #pragma unroll
    for (int s = 0; s < 2; s++) {
        uint32_t stA = sbase + s * STAGE_H * 2;
        uint32_t stB = stA + TILE_H * 2;
        int k0 = s * KC;
        #pragma unroll
        for (int r = 0; r < 2; r++) {
            cp_async16_s(stA + (crow[r] * HSTR + cseg[r] * 8) * 2, Ag + (size_t)crow[r] * NIN + k0 + cseg[r] * 8);
            cp_async16_s(stB + (crow[r] * HSTR + cseg[r] * 8) * 2, Wg + (size_t)crow[r] * NIN + k0 + cseg[r] * 8);
        }
        cp_commit();
    }

    float acc[2][4][4];
    #pragma unroll
    for (int i = 0; i < 2; i++)
        #pragma unroll
        for (int j = 0; j < 4; j++)
            #pragma unroll
            for (int q = 0; q < 4; q++) acc[i][j][q] = 0.f;

    int a_row = wm * 32 + (lane & 15);
    int a_koff = (lane >> 4) * 8;
    int b_row4 = wn * 32 + ((lane >> 4) & 1) * 8 + (lane & 7);
    int b_k4   = ((lane >> 3) & 1) * 8;

    for (int t = 0; t < NCHUNK; t++) {
        cp_wait<1>();
        __syncthreads();
        if (t + 2 < NCHUNK) {
            uint32_t stA = sbase + ((t + 2) % 3) * STAGE_H * 2;
            uint32_t stB = stA + TILE_H * 2;
            int k0 = (t + 2) * KC;
            #pragma unroll
            for (int r = 0; r < 2; r++) {
                cp_async16_s(stA + (crow[r] * HSTR + cseg[r] * 8) * 2, Ag + (size_t)crow[r] * NIN + k0 + cseg[r] * 8);
                cp_async16_s(stB + (crow[r] * HSTR + cseg[r] * 8) * 2, Wg + (size_t)crow[r] * NIN + k0 + cseg[r] * 8);
            }
        }
        cp_commit();

        uint32_t stA = sbase + (t % 3) * STAGE_H * 2;
        uint32_t stB = stA + TILE_H * 2;
        #pragma unroll
        for (int ks = 0; ks < KC; ks += 16) {
            uint32_t af[2][4], bf[4][2];
            #pragma unroll
            for (int i = 0; i < 2; i++)
                ldmatrix_x4(af[i][0], af[i][1], af[i][2], af[i][3],
                            stA + ((a_row + i * 16) * HSTR + ks + a_koff) * 2);
            #pragma unroll
            for (int J = 0; J < 2; J++)
                ldmatrix_x4(bf[2 * J][0], bf[2 * J][1], bf[2 * J + 1][0], bf[2 * J + 1][1],
                            stB + ((b_row4 + J * 16) * HSTR + ks + b_k4) * 2);
            #pragma unroll
            for (int i = 0; i < 2; i++)
                #pragma unroll
                for (int j = 0; j < 4; j++)
                    mma_f16(acc[i][j][0], acc[i][j][1], acc[i][j][2], acc[i][j][3],
                            af[i][0], af[i][1], af[i][2], af[i][3], bf[j][0], bf[j][1]);
        }
    }

    {
        int r0 = lane >> 2, cc = (lane & 3) * 2;
        #pragma unroll
        for (int i = 0; i < 2; i++) {
            size_t rowg0 = (size_t)(bm * 128 + wm * 32 + i * 16 + r0) * TWO_N;
            size_t rowg1 = rowg0 + 8 * TWO_N;
            #pragma unroll
            for (int j = 0; j < 4; j++) {
                int col = bn * 128 + wn * 32 + j * 8 + cc;
                *(float2*)(g_inputs_mul + rowg0 + col) = make_float2(acc[i][j][0], acc[i][j][1]);
                *(float2*)(g_inputs_mul + rowg1 + col) = make_float2(acc[i][j][2], acc[i][j][3]);
            }
        }
    }
}

// ---------------- complex helpers ----------------
__device__ __forceinline__ float2 cadd(float2 a, float2 b){ return make_float2(a.x+b.x, a.y+b.y); }
__device__ __forceinline__ float2 csub(float2 a, float2 b){ return make_float2(a.x-b.x, a.y-b.y); }
__device__ __forceinline__ float2 cmul(float2 a, float2 b){ return make_float2(a.x*b.x - a.y*b.y, a.x*b.y + a.y*b.x); }
template<bool INV> __device__ __forceinline__ float2 mulj(float2 a){
    return INV ? make_float2(-a.y, a.x) : make_float2(a.y, -a.x);
}

template<bool INV>
__device__ __forceinline__ void dft4(float2& a0, float2& a1, float2& a2, float2& a3){
    float2 t0 = cadd(a0, a2), t1 = csub(a0, a2);
    float2 t2 = cadd(a1, a3), t3 = mulj<INV>(csub(a1, a3));
    a0 = cadd(t0, t2); a2 = csub(t0, t2);
    a1 = cadd(t1, t3); a3 = csub(t1, t3);
}

template<bool INV>
__device__ __forceinline__ void dft8(float2 x[8]){
    float2 e0=x[0], e1=x[2], e2=x[4], e3=x[6];
    float2 o0=x[1], o1=x[3], o2=x[5], o3=x[7];
    dft4<INV>(e0, e1, e2, e3);
    dft4<INV>(o0, o1, o2, o3);
    const float c8 = 0.70710678118654752f;
    if (!INV) {
        o1 = make_float2(c8*(o1.x + o1.y), c8*(o1.y - o1.x));
        o2 = make_float2(o2.y, -o2.x);
        o3 = make_float2(c8*(o3.y - o3.x), -c8*(o3.x + o3.y));
    } else {
        o1 = make_float2(c8*(o1.x - o1.y), c8*(o1.x + o1.y));
        o2 = make_float2(-o2.y, o2.x);
        o3 = make_float2(-c8*(o3.x + o3.y), c8*(o3.x - o3.y));
    }
    x[0]=cadd(e0,o0); x[4]=csub(e0,o0);
    x[1]=cadd(e1,o1); x[5]=csub(e1,o1);
    x[2]=cadd(e2,o2); x[6]=csub(e2,o2);
    x[3]=cadd(e3,o3); x[7]=csub(e3,o3);
}

// twiddle powers w^1..w^7 via depth-3 tree
__device__ __forceinline__ void twpow7(float2 w1, float2 w[7]){
    float2 w2 = cmul(w1, w1);
    float2 w3 = cmul(w2, w1);
    float2 w4 = cmul(w2, w2);
    w[0] = w1; w[1] = w2; w[2] = w3; w[3] = w4;
    w[4] = cmul(w2, w3);
    w[5] = cmul(w3, w3);
    w[6] = cmul(w3, w4);
}

// generic middle pass (radix-8, stride S), smem -> smem
template<bool INV, int S>
__device__ __forceinline__ void pass_r8(const float* __restrict__ sre, const float* __restrict__ sim_,
                                        float* __restrict__ dre, float* __restrict__ dim_,
                                        int tid, const float2* __restrict__ tws){
    float2 x[8];
    #pragma unroll
    for (int k = 0; k < 8; k++) { int i = SW(tid + k * 256); x[k] = make_float2(sre[i], sim_[i]); }
    dft8<INV>(x);
    int ps = tid & ~(S - 1);
    int r  = tid &  (S - 1);
    float2 w1 = tws[ps];
    if (INV) w1.y = -w1.y;
    float2 w[7];
    twpow7(w1, w);
    #pragma unroll
    for (int k = 1; k < 8; k++) x[k] = cmul(x[k], w[k - 1]);
    int base = 8 * ps + r;
    #pragma unroll
    for (int k = 0; k < 8; k++) { int i = SW(base + k * S); dre[i] = x[k].x; dim_[i] = x[k].y; }
}

// ---------------- per-row pipeline (round-14 body, b_base param) ----------------
__global__ __launch_bounds__(256, 4) void urnn_row_kernel(
    const float* __restrict__ state,
    const int*   __restrict__ perm,
    const float* __restrict__ bh,
    float* __restrict__ out,
    int b_base) {
    __shared__ float reA[2112], imA[2112], reB[2112], imB[2112];
    __shared__ float2 tws[257];
    __shared__ float2 red[8];

    int tid = threadIdx.x;
    int b   = b_base + blockIdx.x;
    unsigned msk = 0xffffffffu;

    for (int i = tid; i < 257; i += 256) tws[i] = g_tw[i];

    // ---- fwd pass 1 (radix-8, S=1) fused with global load + diag1 ----
    {
        const float* st = state + (size_t)b * TWO_N;
        float2 x[8];
        #pragma unroll
        for (int k = 0; k < 8; k++) {
            int i = tid + k * 256;
            float re = st[i], im = st[i + N_FFT];
            float2 cs = g_d1cs[i];
            x[k] = make_float2(re * cs.x - im * cs.y, re * cs.y + im * cs.x);
        }
        dft8<false>(x);
        float2 w[7];
        twpow7(g_tw[tid], w);
        #pragma unroll
        for (int k = 1; k < 8; k++) x[k] = cmul(x[k], w[k - 1]);
        int base = 8 * tid;
        #pragma unroll
        for (int k = 0; k < 8; k++) { int i = SW(base + k); reA[i] = x[k].x; imA[i] = x[k].y; }
    }
    __syncthreads();

    pass_r8<false, 8 >(reA, imA, reB, imB, tid, tws); __syncthreads();
    pass_r8<false, 64>(reB, imB, reA, imA, tid, tws); __syncthreads();

    float2 f1v;
    // ---- fwd final radix-4: A -> B, dot from registers, ONE barrier ----
    {
        float2 p = make_float2(0.f, 0.f);
        #pragma unroll
        for (int t0 = 0; t0 < 2; t0++) {
            int t = tid + t0 * 256;
            float2 a0 = make_float2(reA[SW(t       )], imA[SW(t       )]);
            float2 a1 = make_float2(reA[SW(t +  512)], imA[SW(t +  512)]);
            float2 a2 = make_float2(reA[SW(t + 1024)], imA[SW(t + 1024)]);
            float2 a3 = make_float2(reA[SW(t + 1536)], imA[SW(t + 1536)]);
            dft4<false>(a0, a1, a2, a3);
            reB[SW(t       )] = a0.x; imB[SW(t       )] = a0.y;
            reB[SW(t +  512)] = a1.x; imB[SW(t +  512)] = a1.y;
            reB[SW(t + 1024)] = a2.x; imB[SW(t + 1024)] = a2.y;
            reB[SW(t + 1536)] = a3.x; imB[SW(t + 1536)] = a3.y;
            float2 zz[4] = {a0, a1, a2, a3};
            #pragma unroll
            for (int q = 0; q < 4; q++) {
                int i = t + q * 512;
                float2 v = g_r1[i];
                p.x += zz[q].x * v.x + zz[q].y * v.y;
                p.y += zz[q].y * v.x - zz[q].x * v.y;
            }
        }
        for (int o = 16; o; o >>= 1) { p.x += __shfl_down_sync(msk, p.x, o); p.y += __shfl_down_sync(msk, p.y, o); }
        if ((tid & 31) == 0) red[tid >> 5] = p;
        __syncthreads();
        float2 q = red[0];
        #pragma unroll
        for (int r = 1; r < 8; r++) { q.x += red[r].x; q.y += red[r].y; }
        float fac = g_fac1;
        f1v = make_float2(q.x * fac, q.y * fac);
    }

    // ---- inv pass 1 (radix-8, S=1) fused with perm gather + reflect-1 apply + diag2 ----
    {
        float2 f = f1v;
        float2 x[8];
        #pragma unroll
        for (int k = 0; k < 8; k++) {
            int i = tid + k * 256;
            int j = perm[i];
            int sj = SW(j);
            float2 v = __ldg(g_r1 + j);
            float2 zz;
            zz.x = reB[sj] - (f.x * v.x - f.y * v.y);
            zz.y = imB[sj] - (f.x * v.y + f.y * v.x);
            x[k] = cmul(zz, g_d2cs[i]);
        }
        dft8<true>(x);
        float2 w1 = tws[tid];
        w1.y = -w1.y;
        float2 w[7];
        twpow7(w1, w);
        #pragma unroll
        for (int k = 1; k < 8; k++) x[k] = cmul(x[k], w[k - 1]);
        int base = 8 * tid;
        #pragma unroll
        for (int k = 0; k < 8; k++) { int i = SW(base + k); reA[i] = x[k].x; imA[i] = x[k].y; }
    }
    __syncthreads();

    pass_r8<true, 8 >(reA, imA, reB, imB, tid, tws); __syncthreads();
    pass_r8<true, 64>(reB, imB, reA, imA, tid, tws); __syncthreads();

    // ---- inv final radix-4 (regs) + reflect-2 dot (ONE barrier) + epilogue ----
    {
        float2 z[8];
        float2 p = make_float2(0.f, 0.f);
        #pragma unroll
        for (int t0 = 0; t0 < 2; t0++) {
            int t = tid + t0 * 256;
            float2 a0 = make_float2(reA[SW(t       )], imA[SW(t       )]);
            float2 a1 = make_float2(reA[SW(t +  512)], imA[SW(t +  512)]);
            float2 a2 = make_float2(reA[SW(t + 1024)], imA[SW(t + 1024)]);
            float2 a3 = make_float2(reA[SW(t + 1536)], imA[SW(t + 1536)]);
            dft4<true>(a0, a1, a2, a3);
            z[t0 * 4 + 0] = a0; z[t0 * 4 + 1] = a1; z[t0 * 4 + 2] = a2; z[t0 * 4 + 3] = a3;
            #pragma unroll
            for (int q = 0; q < 4; q++) {
                int i = t + q * 512;
                float2 v = g_r2[i];
                float2 zz = z[t0 * 4 + q];
                p.x += zz.x * v.x + zz.y * v.y;
                p.y += zz.y * v.x - zz.x * v.y;
            }
        }
        for (int o = 16; o; o >>= 1) { p.x += __shfl_down_sync(msk, p.x, o); p.y += __shfl_down_sync(msk, p.y, o); }
        if ((tid & 31) == 0) red[tid >> 5] = p;
        __syncthreads();
        float2 q = red[0];
        #pragma unroll
        for (int r = 1; r < 8; r++) { q.x += red[r].x; q.y += red[r].y; }
        float fac = g_fac2;
        float2 f = make_float2(q.x * fac, q.y * fac);

        const float* gin = g_inputs_mul + (size_t)b * TWO_N;
        float* ob = out + (size_t)b * TWO_N;
        #pragma unroll
        for (int k = 0; k < 8; k++) {
            int i = tid + (k >> 2) * 256 + (k & 3) * 512;
            float2 v = g_r2[i];
            float2 zz;
            zz.x = z[k].x - (f.x * v.x - f.y * v.y);
            zz.y = z[k].y - (f.x * v.y + f.y * v.x);
            zz = cmul(zz, g_d3cs[i]);              // d3 premultiplied by 1/N
            float pre_r = gin[i]         + zz.x;
            float pre_i = gin[i + N_FFT] + zz.y;
            float nrm = sqrtf(pre_r * pre_r + pre_i * pre_i);
            float sc = fmaxf(nrm + bh[i], 0.f) / (nrm + 1e-6f);
            ob[i]         = pre_r * sc;
            ob[i + N_FFT] = pre_i * sc;
        }
    }
}

// ---------------- launch ----------------
extern "C" void kernel_launch(void* const* d_in, const int* in_sizes, int n_in,
                              void* d_out, int out_size) {
    const float* inputs = (const float*)d_in[0];
    const float* state  = (const float*)d_in[1];
    const float* w_ih   = (const float*)d_in[2];
    const float* b_h    = (const float*)d_in[3];
    const float* d1     = (const float*)d_in[4];
    const float* r1re   = (const float*)d_in[5];
    const float* r1im   = (const float*)d_in[6];
    const float* d2     = (const float*)d_in[7];
    const float* r2re   = (const float*)d_in[8];
    const float* r2im   = (const float*)d_in[9];
    const float* d3     = (const float*)d_in[10];
    const int*   perm   = (const int*)d_in[11];
    float* out = (float*)d_out;

    static cudaStream_t s2 = nullptr;
    static cudaEvent_t evF = nullptr, evSet = nullptr, evG1 = nullptr, evR1 = nullptr;
    if (s2 == nullptr) {
        cudaStreamCreateWithFlags(&s2, cudaStreamNonBlocking);
        cudaEventCreateWithFlags(&evF,  cudaEventDisableTiming);
        cudaEventCreateWithFlags(&evSet, cudaEventDisableTiming);
        cudaEventCreateWithFlags(&evG1, cudaEventDisableTiming);
        cudaEventCreateWithFlags(&evR1, cudaEventDisableTiming);
        cudaFuncSetAttribute(gemm_f16, cudaFuncAttributeMaxDynamicSharedMemorySize, GEMM_SMEM);
    }

    const int HB = BATCH / 2;              // 4096 rows per half
    dim3 gg(TWO_N / 128, BATCH / 128 / 2); // (32, 32) per half

    // fork: setup on s2
    cudaEventRecord(evF, 0);
    cudaStreamWaitEvent(s2, evF, 0);
    setup_kernel<<<1, 1024, 0, s2>>>(d1, r1re, r1im, d2, r2re, r2im, d3);
    cudaEventRecord(evSet, s2);

    // main: convert + GEMM half 1
    convert_kernel<<<(int)(((size_t)BATCH * NIN + (size_t)TWO_N * NIN) / 2048), 256>>>(inputs, w_ih);
    gemm_f16<<<gg, 512, GEMM_SMEM>>>(0);
    cudaEventRecord(evG1, 0);

    // s2: row half 1 (needs setup [stream order] + GEMM half 1)
    cudaStreamWaitEvent(s2, evG1, 0);
    urnn_row_kernel<<<HB, 256, 0, s2>>>(state, perm, b_h, out, 0);
    cudaEventRecord(evR1, s2);

    // main: GEMM half 2 (overlaps with row half 1), then row half 2
    gemm_f16<<<gg, 512, GEMM_SMEM>>>(32);
    cudaStreamWaitEvent(0, evSet, 0);
    urnn_row_kernel<<<HB, 256>>>(state, perm, b_h, out, HB);

    // join row half 1 back to the main stream
    cudaStreamWaitEvent(0, evR1, 0);
}

// round 16
// speedup vs baseline: 1.0685x; 1.0685x over previous
#include <cuda_runtime.h>
#include <cuda_fp16.h>
#include <math.h>
#include <stdint.h>

// URNNCell: out = modrelu( complex(inputs@W^T) + D3·R2·IFFT·D2·P·R1·FFT·D1·state_c )
// B=8192, N_IN=1024, N=2048 (complex), 2N=4096.

#define N_FFT   2048
#define BATCH   8192
#define NIN     1024
#define TWO_N   4096
#define SW(i)   ((i) + ((i) >> 5))

// ---------------- device scratch ----------------
__device__ float  g_inputs_mul[(size_t)BATCH * TWO_N];
__device__ __half g_Ah[(size_t)BATCH * NIN];
__device__ __half g_Wh[(size_t)TWO_N * NIN];
__device__ float2 g_d1cs[N_FFT], g_d2cs[N_FFT], g_d3cs[N_FFT];   // d3 premul by 1/N
__device__ float2 g_r1[N_FFT], g_r2[N_FFT];                      // interleaved reflection vectors
__device__ float2 g_tw[257];
__device__ float  g_fac1, g_fac2;

// ---------------- helpers ----------------
__device__ __forceinline__ uint32_t smem_u32(const void* p) {
    uint32_t a;
    asm("{ .reg .u64 t; cvta.to.shared.u64 t, %1; cvt.u32.u64 %0, t; }" : "=r"(a) : "l"(p));
    return a;
}
__device__ __forceinline__ void cp_async16_s(uint32_t saddr, const void* g) {
    asm volatile("cp.async.cg.shared.global [%0], [%1], 16;\n" :: "r"(saddr), "l"(g));
}
__device__ __forceinline__ void cp_commit() { asm volatile("cp.async.commit_group;\n"); }
template<int N> __device__ __forceinline__ void cp_wait() { asm volatile("cp.async.wait_group %0;\n" :: "n"(N)); }

__device__ __forceinline__ void ldmatrix_x4(uint32_t& r0, uint32_t& r1, uint32_t& r2, uint32_t& r3, uint32_t a) {
    asm volatile("ldmatrix.sync.aligned.m8n8.x4.shared.b16 {%0,%1,%2,%3}, [%4];"
                 : "=r"(r0), "=r"(r1), "=r"(r2), "=r"(r3) : "r"(a));
}
__device__ __forceinline__ void mma_f16(float& c0, float& c1, float& c2, float& c3,
                                        uint32_t a0, uint32_t a1, uint32_t a2, uint32_t a3,
                                        uint32_t b0, uint32_t b1) {
    asm volatile("mma.sync.aligned.m16n8k16.row.col.f32.f16.f16.f32 "
                 "{%0,%1,%2,%3}, {%4,%5,%6,%7}, {%8,%9}, {%0,%1,%2,%3};"
                 : "+f"(c0), "+f"(c1), "+f"(c2), "+f"(c3)
                 : "r"(a0), "r"(a1), "r"(a2), "r"(a3), "r"(b0), "r"(b1));
}

// ---------------- setup (1024 threads, forked stream) ----------------
__global__ void setup_kernel(const float* __restrict__ d1,
                             const float* __restrict__ r1re, const float* __restrict__ r1im,
                             const float* __restrict__ d2,
                             const float* __restrict__ r2re, const float* __restrict__ r2im,
                             const float* __restrict__ d3) {
    int tid = threadIdx.x;   // 1024
    const float invN = 1.f / (float)N_FFT;
    float p1 = 0.f, p2 = 0.f;
    for (int i = tid; i < N_FFT; i += 1024) {
        float s, c;
        sincosf(d1[i], &s, &c); g_d1cs[i] = make_float2(c, s);
        sincosf(d2[i], &s, &c); g_d2cs[i] = make_float2(c, s);
        sincosf(d3[i], &s, &c); g_d3cs[i] = make_float2(c * invN, s * invN);
        float v1r = r1re[i], v1i = r1im[i];
        float v2r = r2re[i], v2i = r2im[i];
        g_r1[i] = make_float2(v1r, v1i);
        g_r2[i] = make_float2(v2r, v2i);
        p1 += v1r * v1r + v1i * v1i;
        p2 += v2r * v2r + v2i * v2i;
    }
    if (tid < 257) {
        float s, c;
        sincosf(-6.283185307179586f * (float)tid / (float)N_FFT, &s, &c);
        g_tw[tid] = make_float2(c, s);
    }
    __shared__ float sh1[32], sh2[32];
    unsigned m = 0xffffffffu;
    for (int o = 16; o; o >>= 1) { p1 += __shfl_down_sync(m, p1, o); p2 += __shfl_down_sync(m, p2, o); }
    int w = tid >> 5, l = tid & 31;
    if (l == 0) { sh1[w] = p1; sh2[w] = p2; }
    __syncthreads();
    if (w == 0) {
        p1 = sh1[l]; p2 = sh2[l];
        for (int o = 16; o; o >>= 1) { p1 += __shfl_down_sync(m, p1, o); p2 += __shfl_down_sync(m, p2, o); }
        if (l == 0) { g_fac1 = 2.f / p1; g_fac2 = 2.f / p2; }
    }
}

// ---------------- fp32 -> fp16 convert ----------------
__global__ __launch_bounds__(256) void convert_kernel(const float* __restrict__ A,
                                                      const float* __restrict__ W) {
    size_t idx = ((size_t)blockIdx.x * 256 + threadIdx.x) * 8;
    const size_t NA = (size_t)BATCH * NIN;
    if (idx < NA) {
        float4 f0 = *(const float4*)(A + idx);
        float4 f1 = *(const float4*)(A + idx + 4);
        __half2* dst = (__half2*)(g_Ah + idx);
        dst[0] = __floats2half2_rn(f0.x, f0.y);
        dst[1] = __floats2half2_rn(f0.z, f0.w);
        dst[2] = __floats2half2_rn(f1.x, f1.y);
        dst[3] = __floats2half2_rn(f1.z, f1.w);
    } else {
        size_t j = idx - NA;
        float4 f0 = *(const float4*)(W + j);
        float4 f1 = *(const float4*)(W + j + 4);
        __half2* dst = (__half2*)(g_Wh + j);
        dst[0] = __floats2half2_rn(f0.x, f0.y);
        dst[1] = __floats2half2_rn(f0.z, f0.w);
        dst[2] = __floats2half2_rn(f1.x, f1.y);
        dst[3] = __floats2half2_rn(f1.z, f1.w);
    }
}

// ---------------- fp16 mma.sync GEMM (round-13 exact) ----------------
#define KC 64
#define NCHUNK (NIN / KC)
#define HSTR 72
#define TILE_H (128 * HSTR)
#define STAGE_H (2 * TILE_H)
#define GEMM_SMEM (3 * STAGE_H * 2)

__global__ __launch_bounds__(512, 2) void gemm_f16() {
    extern __shared__ __half hsm[];
    int tid  = threadIdx.x;
    int lane = tid & 31;
    int warp = tid >> 5;
    int wm = warp >> 2;
    int wn = warp & 3;
    int bm = blockIdx.y, bn = blockIdx.x;

    const __half* Ag = g_Ah + (size_t)bm * 128 * NIN;
    const __half* Wg = g_Wh + (size_t)bn * 128 * NIN;

    int crow[2], cseg[2];
    #pragma unroll
    for (int r = 0; r < 2; r++) { int idx = tid + 512 * r; crow[r] = idx >> 3; cseg[r] = idx & 7; }

    uint32_t sbase = smem_u32(hsm);

    #pragma unroll
    for (int s = 0; s < 2; s++) {
        uint32_t stA = sbase + s * STAGE_H * 2;
        uint32_t stB = stA + TILE_H * 2;
        int k0 = s * KC;
        #pragma unroll
        for (int r = 0; r < 2; r++) {
            cp_async16_s(stA + (crow[r] * HSTR + cseg[r] * 8) * 2, Ag + (size_t)crow[r] * NIN + k0 + cseg[r] * 8);
            cp_async16_s(stB + (crow[r] * HSTR + cseg[r] * 8) * 2, Wg + (size_t)crow[r] * NIN + k0 + cseg[r] * 8);
        }
        cp_commit();
    }

    float acc[2][4][4];
    #pragma unroll
    for (int i = 0; i < 2; i++)
        #pragma unroll
        for (int j = 0; j < 4; j++)
            #pragma unroll
            for (int q = 0; q < 4; q++) acc[i][j][q] = 0.f;

    int a_row = wm * 32 + (lane & 15);
    int a_koff = (lane >> 4) * 8;
    int b_row4 = wn * 32 + ((lane >> 4) & 1) * 8 + (lane & 7);
    int b_k4   = ((lane >> 3) & 1) * 8;

    for (int t = 0; t < NCHUNK; t++) {
        cp_wait<1>();
        __syncthreads();
        if (t + 2 < NCHUNK) {
            uint32_t stA = sbase + ((t + 2) % 3) * STAGE_H * 2;
            uint32_t stB = stA + TILE_H * 2;
            int k0 = (t + 2) * KC;
            #pragma unroll
            for (int r = 0; r < 2; r++) {
                cp_async16_s(stA + (crow[r] * HSTR + cseg[r] * 8) * 2, Ag + (size_t)crow[r] * NIN + k0 + cseg[r] * 8);
                cp_async16_s(stB + (crow[r] * HSTR + cseg[r] * 8) * 2, Wg + (size_t)crow[r] * NIN + k0 + cseg[r] * 8);
            }
        }
        cp_commit();

        uint32_t stA = sbase + (t % 3) * STAGE_H * 2;
        uint32_t stB = stA + TILE_H * 2;
        #pragma unroll
        for (int ks = 0; ks < KC; ks += 16) {
            uint32_t af[2][4], bf[4][2];
            #pragma unroll
            for (int i = 0; i < 2; i++)
                ldmatrix_x4(af[i][0], af[i][1], af[i][2], af[i][3],
                            stA + ((a_row + i * 16) * HSTR + ks + a_koff) * 2);
            #pragma unroll
            for (int J = 0; J < 2; J++)
                ldmatrix_x4(bf[2 * J][0], bf[2 * J][1], bf[2 * J + 1][0], bf[2 * J + 1][1],
                            stB + ((b_row4 + J * 16) * HSTR + ks + b_k4) * 2);
            #pragma unroll
            for (int i = 0; i < 2; i++)
                #pragma unroll
                for (int j = 0; j < 4; j++)
                    mma_f16(acc[i][j][0], acc[i][j][1], acc[i][j][2], acc[i][j][3],
                            af[i][0], af[i][1], af[i][2], af[i][3], bf[j][0], bf[j][1]);
        }
    }

    {
        int r0 = lane >> 2, cc = (lane & 3) * 2;
        #pragma unroll
        for (int i = 0; i < 2; i++) {
            size_t rowg0 = (size_t)(bm * 128 + wm * 32 + i * 16 + r0) * TWO_N;
            size_t rowg1 = rowg0 + 8 * TWO_N;
            #pragma unroll
            for (int j = 0; j < 4; j++) {
                int col = bn * 128 + wn * 32 + j * 8 + cc;
                *(float2*)(g_inputs_mul + rowg0 + col) = make_float2(acc[i][j][0], acc[i][j][1]);
                *(float2*)(g_inputs_mul + rowg1 + col) = make_float2(acc[i][j][2], acc[i][j][3]);
            }
        }
    }
}

// ---------------- complex helpers ----------------
__device__ __forceinline__ float2 cadd(float2 a, float2 b){ return make_float2(a.x+b.x, a.y+b.y); }
__device__ __forceinline__ float2 csub(float2 a, float2 b){ return make_float2(a.x-b.x, a.y-b.y); }
__device__ __forceinline__ float2 cmul(float2 a, float2 b){ return make_float2(a.x*b.x - a.y*b.y, a.x*b.y + a.y*b.x); }
template<bool INV> __device__ __forceinline__ float2 mulj(float2 a){
    return INV ? make_float2(-a.y, a.x) : make_float2(a.y, -a.x);
}

template<bool INV>
__device__ __forceinline__ void dft4(float2& a0, float2& a1, float2& a2, float2& a3){
    float2 t0 = cadd(a0, a2), t1 = csub(a0, a2);
    float2 t2 = cadd(a1, a3), t3 = mulj<INV>(csub(a1, a3));
    a0 = cadd(t0, t2); a2 = csub(t0, t2);
    a1 = cadd(t1, t3); a3 = csub(t1, t3);
}

template<bool INV>
__device__ __forceinline__ void dft8(float2 x[8]){
    float2 e0=x[0], e1=x[2], e2=x[4], e3=x[6];
    float2 o0=x[1], o1=x[3], o2=x[5], o3=x[7];
    dft4<INV>(e0, e1, e2, e3);
    dft4<INV>(o0, o1, o2, o3);
    const float c8 = 0.70710678118654752f;
    if (!INV) {
        o1 = make_float2(c8*(o1.x + o1.y), c8*(o1.y - o1.x));
        o2 = make_float2(o2.y, -o2.x);
        o3 = make_float2(c8*(o3.y - o3.x), -c8*(o3.x + o3.y));
    } else {
        o1 = make_float2(c8*(o1.x - o1.y), c8*(o1.x + o1.y));
        o2 = make_float2(-o2.y, o2.x);
        o3 = make_float2(-c8*(o3.x + o3.y), c8*(o3.x - o3.y));
    }
    x[0]=cadd(e0,o0); x[4]=csub(e0,o0);
    x[1]=cadd(e1,o1); x[5]=csub(e1,o1);
    x[2]=cadd(e2,o2); x[6]=csub(e2,o2);
    x[3]=cadd(e3,o3); x[7]=csub(e3,o3);
}

// twiddle powers w^1..w^7 via depth-3 tree
__device__ __forceinline__ void twpow7(float2 w1, float2 w[7]){
    float2 w2 = cmul(w1, w1);
    float2 w3 = cmul(w2, w1);
    float2 w4 = cmul(w2, w2);
    w[0] = w1; w[1] = w2; w[2] = w3; w[3] = w4;
    w[4] = cmul(w2, w3);
    w[5] = cmul(w3, w3);
    w[6] = cmul(w3, w4);
}

// generic middle pass (radix-8, stride S), smem -> smem
template<bool INV, int S>
__device__ __forceinline__ void pass_r8(const float* __restrict__ sre, const float* __restrict__ sim_,
                                        float* __restrict__ dre, float* __restrict__ dim_,
                                        int tid, const float2* __restrict__ tws){
    float2 x[8];
    #pragma unroll
    for (int k = 0; k < 8; k++) { int i = SW(tid + k * 256); x[k] = make_float2(sre[i], sim_[i]); }
    dft8<INV>(x);
    int ps = tid & ~(S - 1);
    int r  = tid &  (S - 1);
    float2 w1 = tws[ps];
    if (INV) w1.y = -w1.y;
    float2 w[7];
    twpow7(w1, w);
    #pragma unroll
    for (int k = 1; k < 8; k++) x[k] = cmul(x[k], w[k - 1]);
    int base = 8 * ps + r;
    #pragma unroll
    for (int k = 0; k < 8; k++) { int i = SW(base + k * S); dre[i] = x[k].x; dim_[i] = x[k].y; }
}

// ---------------- per-row pipeline ----------------
__global__ __launch_bounds__(256, 4) void urnn_row_kernel(
    const float* __restrict__ state,
    const int*   __restrict__ perm,
    const float* __restrict__ bh,
    float* __restrict__ out) {
    __shared__ float reA[2112], imA[2112], reB[2112], imB[2112];
    __shared__ float2 tws[257];
    __shared__ float2 red[8];

    int tid = threadIdx.x;
    int b   = blockIdx.x;
    unsigned msk = 0xffffffffu;

    for (int i = tid; i < 257; i += 256) tws[i] = g_tw[i];

    // ---- fwd pass 1 (radix-8, S=1) fused with global load + diag1 ----
    {
        const float* st = state + (size_t)b * TWO_N;
        float2 x[8];
        #pragma unroll
        for (int k = 0; k < 8; k++) {
            int i = tid + k * 256;
            float re = st[i], im = st[i + N_FFT];
            float2 cs = g_d1cs[i];
            x[k] = make_float2(re * cs.x - im * cs.y, re * cs.y + im * cs.x);
        }
        dft8<false>(x);
        float2 w[7];
        twpow7(g_tw[tid], w);
        #pragma unroll
        for (int k = 1; k < 8; k++) x[k] = cmul(x[k], w[k - 1]);
        int base = 8 * tid;
        #pragma unroll
        for (int k = 0; k < 8; k++) { int i = SW(base + k); reA[i] = x[k].x; imA[i] = x[k].y; }
    }
    __syncthreads();

    pass_r8<false, 8 >(reA, imA, reB, imB, tid, tws); __syncthreads();
    pass_r8<false, 64>(reB, imB, reA, imA, tid, tws); __syncthreads();

    float2 f1v;
    // ---- fwd final radix-4: A -> B, dot from registers, ONE barrier ----
    {
        float2 p = make_float2(0.f, 0.f);
        #pragma unroll
        for (int t0 = 0; t0 < 2; t0++) {
            int t = tid + t0 * 256;
            float2 a0 = make_float2(reA[SW(t       )], imA[SW(t       )]);
            float2 a1 = make_float2(reA[SW(t +  512)], imA[SW(t +  512)]);
            float2 a2 = make_float2(reA[SW(t + 1024)], imA[SW(t + 1024)]);
            float2 a3 = make_float2(reA[SW(t + 1536)], imA[SW(t + 1536)]);
            dft4<false>(a0, a1, a2, a3);
            reB[SW(t       )] = a0.x; imB[SW(t       )] = a0.y;
            reB[SW(t +  512)] = a1.x; imB[SW(t +  512)] = a1.y;
            reB[SW(t + 1024)] = a2.x; imB[SW(t + 1024)] = a2.y;
            reB[SW(t + 1536)] = a3.x; imB[SW(t + 1536)] = a3.y;
            float2 zz[4] = {a0, a1, a2, a3};
            #pragma unroll
            for (int q = 0; q < 4; q++) {
                int i = t + q * 512;
                float2 v = g_r1[i];
                p.x += zz[q].x * v.x + zz[q].y * v.y;
                p.y += zz[q].y * v.x - zz[q].x * v.y;
            }
        }
        for (int o = 16; o; o >>= 1) { p.x += __shfl_down_sync(msk, p.x, o); p.y += __shfl_down_sync(msk, p.y, o); }
        if ((tid & 31) == 0) red[tid >> 5] = p;
        __syncthreads();
        float2 q = red[0];
        #pragma unroll
        for (int r = 1; r < 8; r++) { q.x += red[r].x; q.y += red[r].y; }
        float fac = g_fac1;
        f1v = make_float2(q.x * fac, q.y * fac);
    }

    // ---- inv pass 1 (radix-8, S=1) fused with perm gather + reflect-1 apply + diag2 ----
    {
        float2 f = f1v;
        float2 x[8];
        #pragma unroll
        for (int k = 0; k < 8; k++) {
            int i = tid + k * 256;
            int j = perm[i];
            int sj = SW(j);
            float2 v = __ldg(g_r1 + j);
            float2 zz;
            zz.x = reB[sj] - (f.x * v.x - f.y * v.y);
            zz.y = imB[sj] - (f.x * v.y + f.y * v.x);
            x[k] = cmul(zz, g_d2cs[i]);
        }
        dft8<true>(x);
        float2 w1 = tws[tid];
        w1.y = -w1.y;
        float2 w[7];
        twpow7(w1, w);
        #pragma unroll
        for (int k = 1; k < 8; k++) x[k] = cmul(x[k], w[k - 1]);
        int base = 8 * tid;
        #pragma unroll
        for (int k = 0; k < 8; k++) { int i = SW(base + k); reA[i] = x[k].x; imA[i] = x[k].y; }
    }
    __syncthreads();

    pass_r8<true, 8 >(reA, imA, reB, imB, tid, tws); __syncthreads();
    pass_r8<true, 64>(reB, imB, reA, imA, tid, tws); __syncthreads();

    // ---- inv final radix-4 (regs) + reflect-2 dot (ONE barrier) + epilogue ----
    {
        float2 z[8];
        float2 p = make_float2(0.f, 0.f);
        #pragma unroll
        for (int t0 = 0; t0 < 2; t0++) {
            int t = tid + t0 * 256;
            float2 a0 = make_float2(reA[SW(t       )], imA[SW(t       )]);
            float2 a1 = make_float2(reA[SW(t +  512)], imA[SW(t +  512)]);
            float2 a2 = make_float2(reA[SW(t + 1024)], imA[SW(t + 1024)]);
            float2 a3 = make_float2(reA[SW(t + 1536)], imA[SW(t + 1536)]);
            dft4<true>(a0, a1, a2, a3);
            z[t0 * 4 + 0] = a0; z[t0 * 4 + 1] = a1; z[t0 * 4 + 2] = a2; z[t0 * 4 + 3] = a3;
            #pragma unroll
            for (int q = 0; q < 4; q++) {
                int i = t + q * 512;
                float2 v = g_r2[i];
                float2 zz = z[t0 * 4 + q];
                p.x += zz.x * v.x + zz.y * v.y;
                p.y += zz.y * v.x - zz.x * v.y;
            }
        }
        for (int o = 16; o; o >>= 1) { p.x += __shfl_down_sync(msk, p.x, o); p.y += __shfl_down_sync(msk, p.y, o); }
        if ((tid & 31) == 0) red[tid >> 5] = p;
        __syncthreads();
        float2 q = red[0];
        #pragma unroll
        for (int r = 1; r < 8; r++) { q.x += red[r].x; q.y += red[r].y; }
        float fac = g_fac2;
        float2 f = make_float2(q.x * fac, q.y * fac);

        const float* gin = g_inputs_mul + (size_t)b * TWO_N;
        float* ob = out + (size_t)b * TWO_N;
        #pragma unroll
        for (int k = 0; k < 8; k++) {
            int i = tid + (k >> 2) * 256 + (k & 3) * 512;
            float2 v = g_r2[i];
            float2 zz;
            zz.x = z[k].x - (f.x * v.x - f.y * v.y);
            zz.y = z[k].y - (f.x * v.y + f.y * v.x);
            zz = cmul(zz, g_d3cs[i]);              // d3 premultiplied by 1/N
            float pre_r = gin[i]         + zz.x;
            float pre_i = gin[i + N_FFT] + zz.y;
            float nrm = sqrtf(pre_r * pre_r + pre_i * pre_i);
            float sc = __fdividef(fmaxf(nrm + bh[i], 0.f), nrm + 1e-6f);
            ob[i]         = pre_r * sc;
            ob[i + N_FFT] = pre_i * sc;
        }
    }
}

// ---------------- launch ----------------
extern "C" void kernel_launch(void* const* d_in, const int* in_sizes, int n_in,
                              void* d_out, int out_size) {
    const float* inputs = (const float*)d_in[0];
    const float* state  = (const float*)d_in[1];
    const float* w_ih   = (const float*)d_in[2];
    const float* b_h    = (const float*)d_in[3];
    const float* d1     = (const float*)d_in[4];
    const float* r1re   = (const float*)d_in[5];
    const float* r1im   = (const float*)d_in[6];
    const float* d2     = (const float*)d_in[7];
    const float* r2re   = (const float*)d_in[8];
    const float* r2im   = (const float*)d_in[9];
    const float* d3     = (const float*)d_in[10];
    const int*   perm   = (const int*)d_in[11];
    float* out = (float*)d_out;

    static cudaStream_t s2 = nullptr;
    static cudaEvent_t evF = nullptr, evJ = nullptr;
    if (s2 == nullptr) {
        cudaStreamCreateWithFlags(&s2, cudaStreamNonBlocking);
        cudaEventCreateWithFlags(&evF, cudaEventDisableTiming);
        cudaEventCreateWithFlags(&evJ, cudaEventDisableTiming);
        cudaFuncSetAttribute(gemm_f16, cudaFuncAttributeMaxDynamicSharedMemorySize, GEMM_SMEM);
    }

    // fork: setup runs on s2 concurrent with convert + GEMM on the main stream
    cudaEventRecord(evF, 0);
    cudaStreamWaitEvent(s2, evF, 0);
    setup_kernel<<<1, 1024, 0, s2>>>(d1, r1re, r1im, d2, r2re, r2im, d3);
    cudaEventRecord(evJ, s2);

    convert_kernel<<<(int)(((size_t)BATCH * NIN + (size_t)TWO_N * NIN) / 2048), 256>>>(inputs, w_ih);
    dim3 gg(TWO_N / 128, BATCH / 128);    // (32, 64)
    gemm_f16<<<gg, 512, GEMM_SMEM>>>();

    // join: row kernel needs setup tables + GEMM output
    cudaStreamWaitEvent(0, evJ, 0);
    urnn_row_kernel<<<BATCH, 256>>>(state, perm, b_h, out);
}

// round 17
// speedup vs baseline: 1.0860x; 1.0163x over previous
#include <cuda_runtime.h>
#include <cuda_fp16.h>
#include <math.h>
#include <stdint.h>

// URNNCell: out = modrelu( complex(inputs@W^T) + D3·R2·IFFT·D2·P·R1·FFT·D1·state_c )
// B=8192, N_IN=1024, N=2048 (complex), 2N=4096.

#define N_FFT   2048
#define BATCH   8192
#define NIN     1024
#define TWO_N   4096
#define SW(i)   ((i) + ((i) >> 5))

// ---------------- device scratch ----------------
__device__ float  g_inputs_mul[(size_t)BATCH * TWO_N];
__device__ __half g_Ah[(size_t)BATCH * NIN];
__device__ __half g_Wh[(size_t)TWO_N * NIN];
__device__ float2 g_d1cs[N_FFT], g_d2cs[N_FFT], g_d3cs[N_FFT];   // d3 premul by 1/N
__device__ float2 g_r1[N_FFT], g_r2[N_FFT];                      // interleaved reflection vectors
__device__ float2 g_tw[257];
__device__ float  g_fac1, g_fac2;

// ---------------- helpers ----------------
__device__ __forceinline__ uint32_t smem_u32(const void* p) {
    uint32_t a;
    asm("{ .reg .u64 t; cvta.to.shared.u64 t, %1; cvt.u32.u64 %0, t; }" : "=r"(a) : "l"(p));
    return a;
}
__device__ __forceinline__ void cp_async16_s(uint32_t saddr, const void* g) {
    asm volatile("cp.async.cg.shared.global [%0], [%1], 16;\n" :: "r"(saddr), "l"(g));
}
__device__ __forceinline__ void cp_commit() { asm volatile("cp.async.commit_group;\n"); }
template<int N> __device__ __forceinline__ void cp_wait() { asm volatile("cp.async.wait_group %0;\n" :: "n"(N)); }

__device__ __forceinline__ void ldmatrix_x4(uint32_t& r0, uint32_t& r1, uint32_t& r2, uint32_t& r3, uint32_t a) {
    asm volatile("ldmatrix.sync.aligned.m8n8.x4.shared.b16 {%0,%1,%2,%3}, [%4];"
                 : "=r"(r0), "=r"(r1), "=r"(r2), "=r"(r3) : "r"(a));
}
__device__ __forceinline__ void mma_f16(float& c0, float& c1, float& c2, float& c3,
                                        uint32_t a0, uint32_t a1, uint32_t a2, uint32_t a3,
                                        uint32_t b0, uint32_t b1) {
    asm volatile("mma.sync.aligned.m16n8k16.row.col.f32.f16.f16.f32 "
                 "{%0,%1,%2,%3}, {%4,%5,%6,%7}, {%8,%9}, {%0,%1,%2,%3};"
                 : "+f"(c0), "+f"(c1), "+f"(c2), "+f"(c3)
                 : "r"(a0), "r"(a1), "r"(a2), "r"(a3), "r"(b0), "r"(b1));
}

// ---------------- setup (1024 threads, forked stream) ----------------
__global__ void setup_kernel(const float* __restrict__ d1,
                             const float* __restrict__ r1re, const float* __restrict__ r1im,
                             const float* __restrict__ d2,
                             const float* __restrict__ r2re, const float* __restrict__ r2im,
                             const float* __restrict__ d3) {
    int tid = threadIdx.x;   // 1024
    const float invN = 1.f / (float)N_FFT;
    float p1 = 0.f, p2 = 0.f;
    for (int i = tid; i < N_FFT; i += 1024) {
        float s, c;
        sincosf(d1[i], &s, &c); g_d1cs[i] = make_float2(c, s);
        sincosf(d2[i], &s, &c); g_d2cs[i] = make_float2(c, s);
        sincosf(d3[i], &s, &c); g_d3cs[i] = make_float2(c * invN, s * invN);
        float v1r = r1re[i], v1i = r1im[i];
        float v2r = r2re[i], v2i = r2im[i];
        g_r1[i] = make_float2(v1r, v1i);
        g_r2[i] = make_float2(v2r, v2i);
        p1 += v1r * v1r + v1i * v1i;
        p2 += v2r * v2r + v2i * v2i;
    }
    if (tid < 257) {
        float s, c;
        sincosf(-6.283185307179586f * (float)tid / (float)N_FFT, &s, &c);
        g_tw[tid] = make_float2(c, s);
    }
    __shared__ float sh1[32], sh2[32];
    unsigned m = 0xffffffffu;
    for (int o = 16; o; o >>= 1) { p1 += __shfl_down_sync(m, p1, o); p2 += __shfl_down_sync(m, p2, o); }
    int w = tid >> 5, l = tid & 31;
    if (l == 0) { sh1[w] = p1; sh2[w] = p2; }
    __syncthreads();
    if (w == 0) {
        p1 = sh1[l]; p2 = sh2[l];
        for (int o = 16; o; o >>= 1) { p1 += __shfl_down_sync(m, p1, o); p2 += __shfl_down_sync(m, p2, o); }
        if (l == 0) { g_fac1 = 2.f / p1; g_fac2 = 2.f / p2; }
    }
}

// ---------------- fp32 -> fp16 convert ----------------
__global__ __launch_bounds__(256) void convert_kernel(const float* __restrict__ A,
                                                      const float* __restrict__ W) {
    size_t idx = ((size_t)blockIdx.x * 256 + threadIdx.x) * 8;
    const size_t NA = (size_t)BATCH * NIN;
    if (idx < NA) {
        float4 f0 = *(const float4*)(A + idx);
        float4 f1 = *(const float4*)(A + idx + 4);
        __half2* dst = (__half2*)(g_Ah + idx);
        dst[0] = __floats2half2_rn(f0.x, f0.y);
        dst[1] = __floats2half2_rn(f0.z, f0.w);
        dst[2] = __floats2half2_rn(f1.x, f1.y);
        dst[3] = __floats2half2_rn(f1.z, f1.w);
    } else {
        size_t j = idx - NA;
        float4 f0 = *(const float4*)(W + j);
        float4 f1 = *(const float4*)(W + j + 4);
        __half2* dst = (__half2*)(g_Wh + j);
        dst[0] = __floats2half2_rn(f0.x, f0.y);
        dst[1] = __floats2half2_rn(f0.z, f0.w);
        dst[2] = __floats2half2_rn(f1.x, f1.y);
        dst[3] = __floats2half2_rn(f1.z, f1.w);
    }
}

// ---------------- fp16 mma.sync GEMM (round-13 exact) ----------------
#define KC 64
#define NCHUNK (NIN / KC)
#define HSTR 72
#define TILE_H (128 * HSTR)
#define STAGE_H (2 * TILE_H)
#define GEMM_SMEM (3 * STAGE_H * 2)

__global__ __launch_bounds__(512, 2) void gemm_f16() {
    extern __shared__ __half hsm[];
    int tid  = threadIdx.x;
    int lane = tid & 31;
    int warp = tid >> 5;
    int wm = warp >> 2;
    int wn = warp & 3;
    int bm = blockIdx.y, bn = blockIdx.x;

    const __half* Ag = g_Ah + (size_t)bm * 128 * NIN;
    const __half* Wg = g_Wh + (size_t)bn * 128 * NIN;

    int crow[2], cseg[2];
    #pragma unroll
    for (int r = 0; r < 2; r++) { int idx = tid + 512 * r; crow[r] = idx >> 3; cseg[r] = idx & 7; }

    uint32_t sbase = smem_u32(hsm);

    #pragma unroll
    for (int s = 0; s < 2; s++) {
        uint32_t stA = sbase + s * STAGE_H * 2;
        uint32_t stB = stA + TILE_H * 2;
        int k0 = s * KC;
        #pragma unroll
        for (int r = 0; r < 2; r++) {
            cp_async16_s(stA + (crow[r] * HSTR + cseg[r] * 8) * 2, Ag + (size_t)crow[r] * NIN + k0 + cseg[r] * 8);
            cp_async16_s(stB + (crow[r] * HSTR + cseg[r] * 8) * 2, Wg + (size_t)crow[r] * NIN + k0 + cseg[r] * 8);
        }
        cp_commit();
    }

    float acc[2][4][4];
    #pragma unroll
    for (int i = 0; i < 2; i++)
        #pragma unroll
        for (int j = 0; j < 4; j++)
            #pragma unroll
            for (int q = 0; q < 4; q++) acc[i][j][q] = 0.f;

    int a_row = wm * 32 + (lane & 15);
    int a_koff = (lane >> 4) * 8;
    int b_row4 = wn * 32 + ((lane >> 4) & 1) * 8 + (lane & 7);
    int b_k4   = ((lane >> 3) & 1) * 8;

    for (int t = 0; t < NCHUNK; t++) {
        cp_wait<1>();
        __syncthreads();
        if (t + 2 < NCHUNK) {
            uint32_t stA = sbase + ((t + 2) % 3) * STAGE_H * 2;
            uint32_t stB = stA + TILE_H * 2;
            int k0 = (t + 2) * KC;
            #pragma unroll
            for (int r = 0; r < 2; r++) {
                cp_async16_s(stA + (crow[r] * HSTR + cseg[r] * 8) * 2, Ag + (size_t)crow[r] * NIN + k0 + cseg[r] * 8);
                cp_async16_s(stB + (crow[r] * HSTR + cseg[r] * 8) * 2, Wg + (size_t)crow[r] * NIN + k0 + cseg[r] * 8);
            }
        }
        cp_commit();

        uint32_t stA = sbase + (t % 3) * STAGE_H * 2;
        uint32_t stB = stA + TILE_H * 2;
        #pragma unroll
        for (int ks = 0; ks < KC; ks += 16) {
            uint32_t af[2][4], bf[4][2];
            #pragma unroll
            for (int i = 0; i < 2; i++)
                ldmatrix_x4(af[i][0], af[i][1], af[i][2], af[i][3],
                            stA + ((a_row + i * 16) * HSTR + ks + a_koff) * 2);
            #pragma unroll
            for (int J = 0; J < 2; J++)
                ldmatrix_x4(bf[2 * J][0], bf[2 * J][1], bf[2 * J + 1][0], bf[2 * J + 1][1],
                            stB + ((b_row4 + J * 16) * HSTR + ks + b_k4) * 2);
            #pragma unroll
            for (int i = 0; i < 2; i++)
                #pragma unroll
                for (int j = 0; j < 4; j++)
                    mma_f16(acc[i][j][0], acc[i][j][1], acc[i][j][2], acc[i][j][3],
                            af[i][0], af[i][1], af[i][2], af[i][3], bf[j][0], bf[j][1]);
        }
    }

    {
        int r0 = lane >> 2, cc = (lane & 3) * 2;
        #pragma unroll
        for (int i = 0; i < 2; i++) {
            size_t rowg0 = (size_t)(bm * 128 + wm * 32 + i * 16 + r0) * TWO_N;
            size_t rowg1 = rowg0 + 8 * TWO_N;
            #pragma unroll
            for (int j = 0; j < 4; j++) {
                int col = bn * 128 + wn * 32 + j * 8 + cc;
                *(float2*)(g_inputs_mul + rowg0 + col) = make_float2(acc[i][j][0], acc[i][j][1]);
                *(float2*)(g_inputs_mul + rowg1 + col) = make_float2(acc[i][j][2], acc[i][j][3]);
            }
        }
    }
}

// ---------------- complex helpers ----------------
__device__ __forceinline__ float2 cadd(float2 a, float2 b){ return make_float2(a.x+b.x, a.y+b.y); }
__device__ __forceinline__ float2 csub(float2 a, float2 b){ return make_float2(a.x-b.x, a.y-b.y); }
__device__ __forceinline__ float2 cmul(float2 a, float2 b){ return make_float2(a.x*b.x - a.y*b.y, a.x*b.y + a.y*b.x); }
template<bool INV> __device__ __forceinline__ float2 mulj(float2 a){
    return INV ? make_float2(-a.y, a.x) : make_float2(a.y, -a.x);
}

template<bool INV>
__device__ __forceinline__ void dft4(float2& a0, float2& a1, float2& a2, float2& a3){
    float2 t0 = cadd(a0, a2), t1 = csub(a0, a2);
    float2 t2 = cadd(a1, a3), t3 = mulj<INV>(csub(a1, a3));
    a0 = cadd(t0, t2); a2 = csub(t0, t2);
    a1 = cadd(t1, t3); a3 = csub(t1, t3);
}

template<bool INV>
__device__ __forceinline__ void dft8(float2 x[8]){
    float2 e0=x[0], e1=x[2], e2=x[4], e3=x[6];
    float2 o0=x[1], o1=x[3], o2=x[5], o3=x[7];
    dft4<INV>(e0, e1, e2, e3);
    dft4<INV>(o0, o1, o2, o3);
    const float c8 = 0.70710678118654752f;
    if (!INV) {
        o1 = make_float2(c8*(o1.x + o1.y), c8*(o1.y - o1.x));
        o2 = make_float2(o2.y, -o2.x);
        o3 = make_float2(c8*(o3.y - o3.x), -c8*(o3.x + o3.y));
    } else {
        o1 = make_float2(c8*(o1.x - o1.y), c8*(o1.x + o1.y));
        o2 = make_float2(-o2.y, o2.x);
        o3 = make_float2(-c8*(o3.x + o3.y), c8*(o3.x - o3.y));
    }
    x[0]=cadd(e0,o0); x[4]=csub(e0,o0);
    x[1]=cadd(e1,o1); x[5]=csub(e1,o1);
    x[2]=cadd(e2,o2); x[6]=csub(e2,o2);
    x[3]=cadd(e3,o3); x[7]=csub(e3,o3);
}

// twiddle powers w^1..w^7 via depth-3 tree
__device__ __forceinline__ void twpow7(float2 w1, float2 w[7]){
    float2 w2 = cmul(w1, w1);
    float2 w3 = cmul(w2, w1);
    float2 w4 = cmul(w2, w2);
    w[0] = w1; w[1] = w2; w[2] = w3; w[3] = w4;
    w[4] = cmul(w2, w3);
    w[5] = cmul(w3, w3);
    w[6] = cmul(w3, w4);
}

// generic middle pass (radix-8, stride S), smem -> smem
template<bool INV, int S>
__device__ __forceinline__ void pass_r8(const float* __restrict__ sre, const float* __restrict__ sim_,
                                        float* __restrict__ dre, float* __restrict__ dim_,
                                        int tid, const float2* __restrict__ tws){
    float2 x[8];
    #pragma unroll
    for (int k = 0; k < 8; k++) { int i = SW(tid + k * 256); x[k] = make_float2(sre[i], sim_[i]); }
    dft8<INV>(x);
    int ps = tid & ~(S - 1);
    int r  = tid &  (S - 1);
    float2 w1 = tws[ps];
    if (INV) w1.y = -w1.y;
    float2 w[7];
    twpow7(w1, w);
    #pragma unroll
    for (int k = 1; k < 8; k++) x[k] = cmul(x[k], w[k - 1]);
    int base = 8 * ps + r;
    #pragma unroll
    for (int k = 0; k < 8; k++) { int i = SW(base + k * S); dre[i] = x[k].x; dim_[i] = x[k].y; }
}

// ---------------- per-row pipeline ----------------
__global__ __launch_bounds__(256, 4) void urnn_row_kernel(
    const float* __restrict__ state,
    const int*   __restrict__ perm,
    const float* __restrict__ bh,
    float* __restrict__ out) {
    __shared__ float reA[2112], imA[2112], reB[2112], imB[2112];
    __shared__ float2 tws[257];
    __shared__ float2 red[8];

    int tid = threadIdx.x;
    int b   = blockIdx.x;
    unsigned msk = 0xffffffffu;

    for (int i = tid; i < 257; i += 256) tws[i] = g_tw[i];

    // ---- fwd pass 1 (radix-8, S=1) fused with global load + diag1 ----
    {
        const float* st = state + (size_t)b * TWO_N;
        float2 x[8];
        #pragma unroll
        for (int k = 0; k < 8; k++) {
            int i = tid + k * 256;
            float re = st[i], im = st[i + N_FFT];
            float2 cs = g_d1cs[i];
            x[k] = make_float2(re * cs.x - im * cs.y, re * cs.y + im * cs.x);
        }
        dft8<false>(x);
        float2 w[7];
        twpow7(g_tw[tid], w);
        #pragma unroll
        for (int k = 1; k < 8; k++) x[k] = cmul(x[k], w[k - 1]);
        int base = 8 * tid;
        #pragma unroll
        for (int k = 0; k < 8; k++) { int i = SW(base + k); reA[i] = x[k].x; imA[i] = x[k].y; }
    }
    __syncthreads();

    pass_r8<false, 8 >(reA, imA, reB, imB, tid, tws); __syncthreads();
    pass_r8<false, 64>(reB, imB, reA, imA, tid, tws); __syncthreads();

    float2 f1v;
    // ---- fwd final radix-4: A -> B, dot from registers, ONE barrier ----
    {
        float2 p = make_float2(0.f, 0.f);
        #pragma unroll
        for (int t0 = 0; t0 < 2; t0++) {
            int t = tid + t0 * 256;
            float2 a0 = make_float2(reA[SW(t       )], imA[SW(t       )]);
            float2 a1 = make_float2(reA[SW(t +  512)], imA[SW(t +  512)]);
            float2 a2 = make_float2(reA[SW(t + 1024)], imA[SW(t + 1024)]);
            float2 a3 = make_float2(reA[SW(t + 1536)], imA[SW(t + 1536)]);
            dft4<false>(a0, a1, a2, a3);
            reB[SW(t       )] = a0.x; imB[SW(t       )] = a0.y;
            reB[SW(t +  512)] = a1.x; imB[SW(t +  512)] = a1.y;
            reB[SW(t + 1024)] = a2.x; imB[SW(t + 1024)] = a2.y;
            reB[SW(t + 1536)] = a3.x; imB[SW(t + 1536)] = a3.y;
            float2 zz[4] = {a0, a1, a2, a3};
            #pragma unroll
            for (int q = 0; q < 4; q++) {
                int i = t + q * 512;
                float2 v = g_r1[i];
                p.x += zz[q].x * v.x + zz[q].y * v.y;
                p.y += zz[q].y * v.x - zz[q].x * v.y;
            }
        }
        for (int o = 16; o; o >>= 1) { p.x += __shfl_down_sync(msk, p.x, o); p.y += __shfl_down_sync(msk, p.y, o); }
        if ((tid & 31) == 0) red[tid >> 5] = p;
        __syncthreads();
        float2 q = red[0];
        #pragma unroll
        for (int r = 1; r < 8; r++) { q.x += red[r].x; q.y += red[r].y; }
        float fac = g_fac1;
        f1v = make_float2(q.x * fac, q.y * fac);
    }

    // ---- inv pass 1 (radix-8, S=1) fused with perm gather + reflect-1 apply + diag2 ----
    {
        float2 f = f1v;
        float2 x[8];
        #pragma unroll
        for (int k = 0; k < 8; k++) {
            int i = tid + k * 256;
            int j = perm[i];
            int sj = SW(j);
            float2 v = __ldg(g_r1 + j);
            float2 zz;
            zz.x = reB[sj] - (f.x * v.x - f.y * v.y);
            zz.y = imB[sj] - (f.x * v.y + f.y * v.x);
            x[k] = cmul(zz, g_d2cs[i]);
        }
        dft8<true>(x);
        float2 w1 = tws[tid];
        w1.y = -w1.y;
        float2 w[7];
        twpow7(w1, w);
        #pragma unroll
        for (int k = 1; k < 8; k++) x[k] = cmul(x[k], w[k - 1]);
        int base = 8 * tid;
        #pragma unroll
        for (int k = 0; k < 8; k++) { int i = SW(base + k); reA[i] = x[k].x; imA[i] = x[k].y; }
    }
    __syncthreads();

    pass_r8<true, 8 >(reA, imA, reB, imB, tid, tws); __syncthreads();
    pass_r8<true, 64>(reB, imB, reA, imA, tid, tws); __syncthreads();

    // ---- inv final radix-4 (regs) + reflect-2 dot (ONE barrier) + epilogue ----
    {
        float2 z[8];
        float2 p = make_float2(0.f, 0.f);
        #pragma unroll
        for (int t0 = 0; t0 < 2; t0++) {
            int t = tid + t0 * 256;
            float2 a0 = make_float2(reA[SW(t       )], imA[SW(t       )]);
            float2 a1 = make_float2(reA[SW(t +  512)], imA[SW(t +  512)]);
            float2 a2 = make_float2(reA[SW(t + 1024)], imA[SW(t + 1024)]);
            float2 a3 = make_float2(reA[SW(t + 1536)], imA[SW(t + 1536)]);
            dft4<true>(a0, a1, a2, a3);
            z[t0 * 4 + 0] = a0; z[t0 * 4 + 1] = a1; z[t0 * 4 + 2] = a2; z[t0 * 4 + 3] = a3;
            #pragma unroll
            for (int q = 0; q < 4; q++) {
                int i = t + q * 512;
                float2 v = g_r2[i];
                float2 zz = z[t0 * 4 + q];
                p.x += zz.x * v.x + zz.y * v.y;
                p.y += zz.y * v.x - zz.x * v.y;
            }
        }
        for (int o = 16; o; o >>= 1) { p.x += __shfl_down_sync(msk, p.x, o); p.y += __shfl_down_sync(msk, p.y, o); }
        if ((tid & 31) == 0) red[tid >> 5] = p;
        __syncthreads();
        float2 q = red[0];
        #pragma unroll
        for (int r = 1; r < 8; r++) { q.x += red[r].x; q.y += red[r].y; }
        float fac = g_fac2;
        float2 f = make_float2(q.x * fac, q.y * fac);

        const float* gin = g_inputs_mul + (size_t)b * TWO_N;
        float* ob = out + (size_t)b * TWO_N;
        #pragma unroll
        for (int k = 0; k < 8; k++) {
            int i = tid + (k >> 2) * 256 + (k & 3) * 512;
            float2 v = g_r2[i];
            float2 zz;
            zz.x = z[k].x - (f.x * v.x - f.y * v.y);
            zz.y = z[k].y - (f.x * v.y + f.y * v.x);
            zz = cmul(zz, g_d3cs[i]);              // d3 premultiplied by 1/N
            float pre_r = gin[i]         + zz.x;
            float pre_i = gin[i + N_FFT] + zz.y;
            float sq  = fmaxf(pre_r * pre_r + pre_i * pre_i, 1e-24f);
            float nrm = sq * __frsqrt_rn(sq);      // fast |z| (MUFU.RSQ + MUL)
            float sc  = __fdividef(fmaxf(nrm + bh[i], 0.f), nrm + 1e-6f);
            ob[i]         = pre_r * sc;
            ob[i + N_FFT] = pre_i * sc;
        }
    }
}

// ---------------- launch ----------------
extern "C" void kernel_launch(void* const* d_in, const int* in_sizes, int n_in,
                              void* d_out, int out_size) {
    const float* inputs = (const float*)d_in[0];
    const float* state  = (const float*)d_in[1];
    const float* w_ih   = (const float*)d_in[2];
    const float* b_h    = (const float*)d_in[3];
    const float* d1     = (const float*)d_in[4];
    const float* r1re   = (const float*)d_in[5];
    const float* r1im   = (const float*)d_in[6];
    const float* d2     = (const float*)d_in[7];
    const float* r2re   = (const float*)d_in[8];
    const float* r2im   = (const float*)d_in[9];
    const float* d3     = (const float*)d_in[10];
    const int*   perm   = (const int*)d_in[11];
    float* out = (float*)d_out;

    static cudaStream_t s2 = nullptr;
    static cudaEvent_t evF = nullptr, evJ = nullptr;
    if (s2 == nullptr) {
        cudaStreamCreateWithFlags(&s2, cudaStreamNonBlocking);
        cudaEventCreateWithFlags(&evF, cudaEventDisableTiming);
        cudaEventCreateWithFlags(&evJ, cudaEventDisableTiming);
        cudaFuncSetAttribute(gemm_f16, cudaFuncAttributeMaxDynamicSharedMemorySize, GEMM_SMEM);
    }

    // fork: setup runs on s2 concurrent with convert + GEMM on the main stream
    cudaEventRecord(evF, 0);
    cudaStreamWaitEvent(s2, evF, 0);
    setup_kernel<<<1, 1024, 0, s2>>>(d1, r1re, r1im, d2, r2re, r2im, d3);
    cudaEventRecord(evJ, s2);

    convert_kernel<<<(int)(((size_t)BATCH * NIN + (size_t)TWO_N * NIN) / 2048), 256>>>(inputs, w_ih);
    dim3 gg(TWO_N / 128, BATCH / 128);    // (32, 64)
    gemm_f16<<<gg, 512, GEMM_SMEM>>>();

    // join: row kernel needs setup tables + GEMM output
    cudaStreamWaitEvent(0, evJ, 0);
    urnn_row_kernel<<<BATCH, 256>>>(state, perm, b_h, out);
}